// round 2
// baseline (speedup 1.0000x reference)
#include <cuda_runtime.h>

#define WS 8
#define BB 64
#define TT 256
#define HH 64
#define FIN 4
#define NW 248      // number of windows / predictions
#define GATES 256   // 4*H

__device__ __forceinline__ float sigm(float x) {
    return __fdividef(1.0f, 1.0f + __expf(-x));
}
__device__ __forceinline__ float tanh_fast(float x) {
    // tanh(x) = 2*sigmoid(2x) - 1
    return __fdividef(2.0f, 1.0f + __expf(-2.0f * x)) - 1.0f;
}

__global__ __launch_bounds__(256, 1)
void or_lstm_kernel(const float* __restrict__ traj,
                    const float* __restrict__ Wih0, const float* __restrict__ Whh0,
                    const float* __restrict__ bih0, const float* __restrict__ bhh0,
                    const float* __restrict__ Wih1, const float* __restrict__ Whh1,
                    const float* __restrict__ bih1, const float* __restrict__ bhh1,
                    const float* __restrict__ Wlin, const float* __restrict__ blin,
                    float* __restrict__ out)
{
    const int b   = blockIdx.x;
    const int tid = threadIdx.x;
    const int j   = tid;   // gate index this thread owns (0..255)

    __shared__ float trajs[TT * FIN];     // this batch row's trajectory (4 KB)
    __shared__ float h0s[HH];
    __shared__ float h1s[HH];
    __shared__ float gbuf[GATES];
    __shared__ float preds[NW * 2];
    __shared__ float xin[4];
    __shared__ float red[128];
    __shared__ float wlin_s[128];
    __shared__ float blin_s[2];

    // ---- stage trajectory + lin weights into smem ----
    for (int i = tid; i < TT * FIN; i += 256) trajs[i] = traj[b * TT * FIN + i];
    if (tid < 128) wlin_s[tid] = Wlin[tid];
    if (tid < 2)   blin_s[tid] = blin[tid];

    // ---- weights -> registers (thread j owns row j of every weight matrix) ----
    float wih0[FIN], whh0[HH], wih1[HH], whh1[HH];
    {
        const float4* p = (const float4*)(Wih0 + j * FIN);
        float4 v = p[0];
        wih0[0] = v.x; wih0[1] = v.y; wih0[2] = v.z; wih0[3] = v.w;
    }
    #pragma unroll
    for (int k = 0; k < HH; k += 4) {
        float4 v = *(const float4*)(Whh0 + j * HH + k);
        whh0[k] = v.x; whh0[k+1] = v.y; whh0[k+2] = v.z; whh0[k+3] = v.w;
    }
    #pragma unroll
    for (int k = 0; k < HH; k += 4) {
        float4 v = *(const float4*)(Wih1 + j * HH + k);
        wih1[k] = v.x; wih1[k+1] = v.y; wih1[k+2] = v.z; wih1[k+3] = v.w;
    }
    #pragma unroll
    for (int k = 0; k < HH; k += 4) {
        float4 v = *(const float4*)(Whh1 + j * HH + k);
        whh1[k] = v.x; whh1[k+1] = v.y; whh1[k+2] = v.z; whh1[k+3] = v.w;
    }
    const float bias0 = bih0[j] + bhh0[j];
    const float bias1 = bih1[j] + bhh1[j];

    float c0 = 0.0f, c1 = 0.0f;   // cell states, owned by tid < 64

    for (int w = 0; w < NW; w++) {
        // fresh zero state for every window
        if (tid < HH) { h0s[tid] = 0.0f; h1s[tid] = 0.0f; }
        c0 = 0.0f; c1 = 0.0f;

        for (int s = 0; s < WS; s++) {
            // ---- build this step's 4-feature input row ----
            if (tid < 4) {
                const int f = tid;
                float v;
                if (w == 0) {
                    v = trajs[s * FIN + f];
                } else if (w < WS) {
                    if (s < WS - w) {
                        v = trajs[(w + s) * FIN + f];
                    } else {
                        v = (f < 2) ? trajs[(2 * w + s - 1) * FIN + f]
                                    : preds[(w + s - WS) * 2 + (f - 2)];
                    }
                } else {
                    v = (f < 2) ? trajs[(w + s) * FIN + f]
                                : preds[(w + s - WS) * 2 + (f - 2)];
                }
                xin[f] = v;
            }
            __syncthreads();   // (A) xin + h state ready

            // ---- layer 0 gate GEMV: g = Wih0*x + Whh0*h0 + b ----
            float a0 = bias0, a1 = 0.0f, a2 = 0.0f, a3 = 0.0f;
            {
                float4 xv = *(const float4*)&xin[0];
                a0 += xv.x * wih0[0]; a1 += xv.y * wih0[1];
                a2 += xv.z * wih0[2]; a3 += xv.w * wih0[3];
            }
            #pragma unroll
            for (int k = 0; k < HH; k += 4) {
                float4 hv = *(const float4*)&h0s[k];
                a0 += hv.x * whh0[k];     a1 += hv.y * whh0[k + 1];
                a2 += hv.z * whh0[k + 2]; a3 += hv.w * whh0[k + 3];
            }
            gbuf[j] = (a0 + a1) + (a2 + a3);
            __syncthreads();   // (B) gates ready

            if (tid < HH) {
                float ig = sigm(gbuf[tid]);
                float fg = sigm(gbuf[tid + 64]);
                float gg = tanh_fast(gbuf[tid + 128]);
                float og = sigm(gbuf[tid + 192]);
                c0 = fg * c0 + ig * gg;
                h0s[tid] = og * tanh_fast(c0);
            }
            __syncthreads();   // (C) h0 updated

            // ---- layer 1 gate GEMV: g = Wih1*h0 + Whh1*h1 + b ----
            a0 = bias1; a1 = 0.0f; a2 = 0.0f; a3 = 0.0f;
            #pragma unroll
            for (int k = 0; k < HH; k += 4) {
                float4 hv = *(const float4*)&h0s[k];
                a0 += hv.x * wih1[k];     a1 += hv.y * wih1[k + 1];
                a2 += hv.z * wih1[k + 2]; a3 += hv.w * wih1[k + 3];
            }
            #pragma unroll
            for (int k = 0; k < HH; k += 4) {
                float4 hv = *(const float4*)&h1s[k];
                a0 += hv.x * whh1[k];     a1 += hv.y * whh1[k + 1];
                a2 += hv.z * whh1[k + 2]; a3 += hv.w * whh1[k + 3];
            }
            gbuf[j] = (a0 + a1) + (a2 + a3);
            __syncthreads();   // (D) gates ready

            if (tid < HH) {
                float ig = sigm(gbuf[tid]);
                float fg = sigm(gbuf[tid + 64]);
                float gg = tanh_fast(gbuf[tid + 128]);
                float og = sigm(gbuf[tid + 192]);
                c1 = fg * c1 + ig * gg;
                h1s[tid] = og * tanh_fast(c1);
            }
            __syncthreads();   // h1 visible for next step / lin
        }

        // ---- prediction: p[w] = p[w-1] + Wlin * h1_last + blin ----
        if (tid < 128) {
            const int r = tid >> 6, k = tid & 63;
            red[tid] = wlin_s[r * 64 + k] * h1s[k];
        }
        __syncthreads();
        if (tid < 2) {
            float d = blin_s[tid];
            #pragma unroll
            for (int k = 0; k < 64; k++) d += red[tid * 64 + k];
            const float prev = (w == 0) ? trajs[7 * FIN + 2 + tid]
                                        : preds[(w - 1) * 2 + tid];
            const float p = prev + d;
            preds[w * 2 + tid] = p;
            out[(b * NW + w) * 2 + tid] = p;
        }
        __syncthreads();
    }

    // ---- final hidden/cell states from the last window (layout [2,B,H]) ----
    if (tid < HH) {
        const int base = BB * NW * 2;          // 31744
        out[base + 0 * BB * HH + b * HH + tid] = h0s[tid];
        out[base + 1 * BB * HH + b * HH + tid] = h1s[tid];
        out[base + 2 * BB * HH + 0 * BB * HH + b * HH + tid] = c0;
        out[base + 2 * BB * HH + 1 * BB * HH + b * HH + tid] = c1;
    }
}

extern "C" void kernel_launch(void* const* d_in, const int* in_sizes, int n_in,
                              void* d_out, int out_size) {
    const float* traj = (const float*)d_in[0];
    const float* Wih0 = (const float*)d_in[1];
    const float* Whh0 = (const float*)d_in[2];
    const float* bih0 = (const float*)d_in[3];
    const float* bhh0 = (const float*)d_in[4];
    const float* Wih1 = (const float*)d_in[5];
    const float* Whh1 = (const float*)d_in[6];
    const float* bih1 = (const float*)d_in[7];
    const float* bhh1 = (const float*)d_in[8];
    const float* Wlin = (const float*)d_in[9];
    const float* blin = (const float*)d_in[10];

    or_lstm_kernel<<<BB, 256>>>(traj, Wih0, Whh0, bih0, bhh0,
                                Wih1, Whh1, bih1, bhh1,
                                Wlin, blin, (float*)d_out);
}

// round 3
// speedup vs baseline: 1.2117x; 1.2117x over previous
#include <cuda_runtime.h>

#define WS 8
#define BB 64
#define TT 256
#define HH 64
#define FIN 4
#define NW 248

typedef unsigned long long u64;

__device__ __forceinline__ void fma2(u64 &acc, u64 a, u64 b) {
    asm("fma.rn.f32x2 %0, %1, %2, %0;" : "+l"(acc) : "l"(a), "l"(b));
}
__device__ __forceinline__ void add2(u64 &a, u64 b) {
    asm("add.rn.f32x2 %0, %1, %2;" : "=l"(a) : "l"(a), "l"(b));
}
__device__ __forceinline__ float lo_f(u64 v) { return __uint_as_float((unsigned)v); }
__device__ __forceinline__ float hi_f(u64 v) { return __uint_as_float((unsigned)(v >> 32)); }
__device__ __forceinline__ float tanh_ap(float x) {
    float y; asm("tanh.approx.f32 %0, %1;" : "=f"(y) : "f"(x)); return y;
}
__device__ __forceinline__ float sigm(float x) {
    return fmaf(0.5f, tanh_ap(0.5f * x), 0.5f);
}

__global__ __launch_bounds__(256, 1)
void or_lstm_kernel(const float* __restrict__ traj,
                    const float* __restrict__ Wih0, const float* __restrict__ Whh0,
                    const float* __restrict__ bih0, const float* __restrict__ bhh0,
                    const float* __restrict__ Wih1, const float* __restrict__ Whh1,
                    const float* __restrict__ bih1, const float* __restrict__ bhh1,
                    const float* __restrict__ Wlin, const float* __restrict__ blin,
                    float* __restrict__ out)
{
    const int b   = blockIdx.x;
    const int tid = threadIdx.x;
    const int j   = tid;

    __shared__ __align__(16) float trajs[TT * FIN];
    __shared__ __align__(16) float h0s[HH];
    __shared__ __align__(16) float h1s[HH];
    __shared__ __align__(16) float g0buf[256];   // activated layer-0 gates
    __shared__ __align__(16) float g1buf[256];   // activated layer-1 gates
    __shared__ __align__(16) float xin[WS][FIN]; // this window's 8 input rows
    __shared__ float preds[NW * 2];
    __shared__ float red[128];
    __shared__ float wlin_s[128];
    __shared__ float blin_s[2];

    // ---- stage trajectory + lin weights ----
    for (int i = tid; i < TT * FIN; i += 256) trajs[i] = traj[b * TT * FIN + i];
    if (tid < 128) wlin_s[tid] = Wlin[tid];
    if (tid < 2)   blin_s[tid] = blin[tid];

    // ---- weights -> packed register pairs (thread j owns gate row j) ----
    u64 wih0[2], whh0[32], wih1[32], whh1[32];
    {
        ulonglong2 v = *(const ulonglong2*)(Wih0 + j * FIN);
        wih0[0] = v.x; wih0[1] = v.y;
    }
    #pragma unroll
    for (int k = 0; k < 16; k++) {
        ulonglong2 v = ((const ulonglong2*)(Whh0 + j * HH))[k];
        whh0[2 * k] = v.x; whh0[2 * k + 1] = v.y;
    }
    #pragma unroll
    for (int k = 0; k < 16; k++) {
        ulonglong2 v = ((const ulonglong2*)(Wih1 + j * HH))[k];
        wih1[2 * k] = v.x; wih1[2 * k + 1] = v.y;
    }
    #pragma unroll
    for (int k = 0; k < 16; k++) {
        ulonglong2 v = ((const ulonglong2*)(Whh1 + j * HH))[k];
        whh1[2 * k] = v.x; whh1[2 * k + 1] = v.y;
    }
    const u64 bias0p = (u64)__float_as_uint(bih0[j] + bhh0[j]);  // lane0 = bias, lane1 = 0
    const u64 bias1p = (u64)__float_as_uint(bih1[j] + bhh1[j]);

    const bool is_g = (j >= 128) && (j < 192);   // tanh gate, others sigmoid
    float c0 = 0.0f, c1 = 0.0f;

    __syncthreads();   // trajs staged

    for (int w = 0; w < NW; w++) {
        // ---- build all 8 input rows for this window (reads only prior preds) ----
        if (tid < 32) {
            const int s = tid >> 2, f = tid & 3;
            float v;
            if (w == 0) {
                v = trajs[s * FIN + f];
            } else if (w < WS) {
                if (s < WS - w) {
                    v = trajs[(w + s) * FIN + f];
                } else {
                    v = (f < 2) ? trajs[(2 * w + s - 1) * FIN + f]
                                : preds[(w + s - WS) * 2 + (f - 2)];
                }
            } else {
                v = (f < 2) ? trajs[(w + s) * FIN + f]
                            : preds[(w + s - WS) * 2 + (f - 2)];
            }
            xin[s][f] = v;
        }
        __syncthreads();

        // ---- prologue: g0(0) = act(bias0 + Wih0·x0)  (h0 = 0, skip Whh0 term) ----
        {
            u64 a0 = bias0p, a1 = 0;
            const u64* xp = (const u64*)&xin[0][0];
            fma2(a0, xp[0], wih0[0]);
            fma2(a1, xp[1], wih0[1]);
            add2(a0, a1);
            float g = lo_f(a0) + hi_f(a0);
            g0buf[j] = is_g ? tanh_ap(g) : sigm(g);
        }
        __syncthreads();   // "E": g0(0) ready

        for (int s = 0; s < WS; s++) {
            // ---- PA: epi0 -> h0(s); all threads: part1 = Whh1·h1(s-1) ----
            u64 p0 = 0, p1 = 0, p2 = 0, p3 = 0;
            if (s > 0) {
                const ulonglong2* hp = (const ulonglong2*)h1s;
                #pragma unroll
                for (int k = 0; k < 8; k++) {
                    ulonglong2 va = hp[2 * k];
                    ulonglong2 vb = hp[2 * k + 1];
                    fma2(p0, va.x, whh1[4 * k + 0]);
                    fma2(p1, va.y, whh1[4 * k + 1]);
                    fma2(p2, vb.x, whh1[4 * k + 2]);
                    fma2(p3, vb.y, whh1[4 * k + 3]);
                }
            }
            if (tid < HH) {
                float ig = g0buf[tid], fg = g0buf[tid + 64];
                float gg = g0buf[tid + 128], og = g0buf[tid + 192];
                c0 = (s == 0) ? ig * gg : fmaf(fg, c0, ig * gg);
                h0s[tid] = og * tanh_ap(c0);
            }
            __syncthreads();   // C: h0(s) ready

            // ---- PB: g1 = act(bias1 + part1 + Wih1·h0(s)) ----
            {
                u64 a0 = bias1p, a1 = 0, a2 = 0, a3 = 0;
                const ulonglong2* hp = (const ulonglong2*)h0s;
                #pragma unroll
                for (int k = 0; k < 8; k++) {
                    ulonglong2 va = hp[2 * k];
                    ulonglong2 vb = hp[2 * k + 1];
                    fma2(a0, va.x, wih1[4 * k + 0]);
                    fma2(a1, va.y, wih1[4 * k + 1]);
                    fma2(a2, vb.x, wih1[4 * k + 2]);
                    fma2(a3, vb.y, wih1[4 * k + 3]);
                }
                add2(a0, p0); add2(a1, p1); add2(a2, p2); add2(a3, p3);
                add2(a0, a1); add2(a2, a3); add2(a0, a2);
                float g = lo_f(a0) + hi_f(a0);
                g1buf[j] = is_g ? tanh_ap(g) : sigm(g);
            }
            __syncthreads();   // D: g1 ready

            // ---- PC: epi1 -> h1(s); all threads: full g0(s+1) (h0(s) is final) ----
            if (s < WS - 1) {
                u64 a0 = bias0p, a1 = 0, a2 = 0, a3 = 0;
                const u64* xp = (const u64*)&xin[s + 1][0];
                fma2(a0, xp[0], wih0[0]);
                fma2(a1, xp[1], wih0[1]);
                const ulonglong2* hp = (const ulonglong2*)h0s;
                #pragma unroll
                for (int k = 0; k < 8; k++) {
                    ulonglong2 va = hp[2 * k];
                    ulonglong2 vb = hp[2 * k + 1];
                    fma2(a0, va.x, whh0[4 * k + 0]);
                    fma2(a1, va.y, whh0[4 * k + 1]);
                    fma2(a2, vb.x, whh0[4 * k + 2]);
                    fma2(a3, vb.y, whh0[4 * k + 3]);
                }
                add2(a0, a1); add2(a2, a3); add2(a0, a2);
                float g = lo_f(a0) + hi_f(a0);
                float act = is_g ? tanh_ap(g) : sigm(g);
                if (tid < HH) {
                    float ig = g1buf[tid], fg = g1buf[tid + 64];
                    float gg = g1buf[tid + 128], og = g1buf[tid + 192];
                    c1 = (s == 0) ? ig * gg : fmaf(fg, c1, ig * gg);
                    h1s[tid] = og * tanh_ap(c1);
                }
                g0buf[j] = act;
            } else {
                if (tid < HH) {
                    float ig = g1buf[tid], fg = g1buf[tid + 64];
                    float gg = g1buf[tid + 128], og = g1buf[tid + 192];
                    c1 = (s == 0) ? ig * gg : fmaf(fg, c1, ig * gg);
                    h1s[tid] = og * tanh_ap(c1);
                }
            }
            __syncthreads();   // E: h1(s) (and g0(s+1)) ready
        }

        // ---- prediction: p[w] = p[w-1] + Wlin·h1_last + blin ----
        if (tid < 128) {
            const int r = tid >> 6, k = tid & 63;
            red[tid] = wlin_s[r * 64 + k] * h1s[k];
        }
        __syncthreads();
        if (tid < 2) {
            float d = blin_s[tid];
            #pragma unroll
            for (int k = 0; k < 64; k++) d += red[tid * 64 + k];
            const float prev = (w == 0) ? trajs[7 * FIN + 2 + tid]
                                        : preds[(w - 1) * 2 + tid];
            const float p = prev + d;
            preds[w * 2 + tid] = p;
            out[(b * NW + w) * 2 + tid] = p;
        }
        __syncthreads();
    }

    // ---- final hidden/cell states (layout: h[2,B,H] then c[2,B,H]) ----
    if (tid < HH) {
        const int base = BB * NW * 2;
        out[base + 0 * BB * HH + b * HH + tid] = h0s[tid];
        out[base + 1 * BB * HH + b * HH + tid] = h1s[tid];
        out[base + 2 * BB * HH + 0 * BB * HH + b * HH + tid] = c0;
        out[base + 2 * BB * HH + 1 * BB * HH + b * HH + tid] = c1;
    }
}

extern "C" void kernel_launch(void* const* d_in, const int* in_sizes, int n_in,
                              void* d_out, int out_size) {
    const float* traj = (const float*)d_in[0];
    const float* Wih0 = (const float*)d_in[1];
    const float* Whh0 = (const float*)d_in[2];
    const float* bih0 = (const float*)d_in[3];
    const float* bhh0 = (const float*)d_in[4];
    const float* Wih1 = (const float*)d_in[5];
    const float* Whh1 = (const float*)d_in[6];
    const float* bih1 = (const float*)d_in[7];
    const float* bhh1 = (const float*)d_in[8];
    const float* Wlin = (const float*)d_in[9];
    const float* blin = (const float*)d_in[10];

    or_lstm_kernel<<<BB, 256>>>(traj, Wih0, Whh0, bih0, bhh0,
                                Wih1, Whh1, bih1, bhh1,
                                Wlin, blin, (float*)d_out);
}

// round 4
// speedup vs baseline: 1.5380x; 1.2693x over previous
#include <cuda_runtime.h>

#define WS 8
#define BB 64
#define TT 256
#define HH 64
#define FIN 4
#define NW 248

typedef unsigned long long u64;

__device__ __forceinline__ void fma2(u64 &acc, u64 a, u64 b) {
    asm("fma.rn.f32x2 %0, %1, %2, %0;" : "+l"(acc) : "l"(a), "l"(b));
}
__device__ __forceinline__ void add2(u64 &a, u64 b) {
    asm("add.rn.f32x2 %0, %1, %2;" : "=l"(a) : "l"(a), "l"(b));
}
__device__ __forceinline__ u64 pack2(float a, float b) {
    u64 r; asm("mov.b64 %0, {%1, %2};" : "=l"(r) : "f"(a), "f"(b)); return r;
}
__device__ __forceinline__ float lo_f(u64 v) { return __uint_as_float((unsigned)v); }
__device__ __forceinline__ float hi_f(u64 v) { return __uint_as_float((unsigned)(v >> 32)); }
__device__ __forceinline__ float tanh_ap(float x) {
    float y; asm("tanh.approx.f32 %0, %1;" : "=f"(y) : "f"(x)); return y;
}
__device__ __forceinline__ float sigm(float x) {
    return fmaf(0.5f, tanh_ap(0.5f * x), 0.5f);
}
__device__ __forceinline__ u64 shflx(u64 v, int mask) {
    unsigned lo = (unsigned)v, hi = (unsigned)(v >> 32);
    lo = __shfl_xor_sync(0xffffffffu, lo, mask);
    hi = __shfl_xor_sync(0xffffffffu, hi, mask);
    return ((u64)hi << 32) | lo;
}

// acc[g] += W[g] · h_slice  (16 k-elements, chunks 16c+4sl)
__device__ __forceinline__ void dot64(u64 acc[4], const float* __restrict__ hbuf,
                                      const u64 (&w)[4][4][2], int sl) {
    #pragma unroll
    for (int c = 0; c < 4; c++) {
        ulonglong2 hv = *(const ulonglong2*)(hbuf + 16 * c + 4 * sl);
        #pragma unroll
        for (int g = 0; g < 4; g++) {
            fma2(acc[g], hv.x, w[g][c][0]);
            fma2(acc[g], hv.y, w[g][c][1]);
        }
    }
}

// cross-slice reduce + bias + LSTM cell; returns h, updates c. All 4 lanes of a
// group compute identical results (deterministic).
__device__ __forceinline__ float cell_epi(u64 acc[4], u64 X0, u64 X1,
                                          u64 b0, u64 b1, float &c, bool first) {
    u64 A = X0, B = X1;
    add2(A, pack2(lo_f(acc[0]) + hi_f(acc[0]), lo_f(acc[1]) + hi_f(acc[1])));
    add2(B, pack2(lo_f(acc[2]) + hi_f(acc[2]), lo_f(acc[3]) + hi_f(acc[3])));
    add2(A, shflx(A, 1)); add2(A, shflx(A, 2));
    add2(B, shflx(B, 1)); add2(B, shflx(B, 2));
    add2(A, b0); add2(B, b1);
    float ig = sigm(lo_f(A)), fg = sigm(hi_f(A));
    float gg = tanh_ap(lo_f(B)), og = sigm(hi_f(B));
    c = first ? ig * gg : fmaf(fg, c, ig * gg);
    return og * tanh_ap(c);
}

__global__ __launch_bounds__(256, 1)
void or_lstm_kernel(const float* __restrict__ traj,
                    const float* __restrict__ Wih0, const float* __restrict__ Whh0,
                    const float* __restrict__ bih0, const float* __restrict__ bhh0,
                    const float* __restrict__ Wih1, const float* __restrict__ Whh1,
                    const float* __restrict__ bih1, const float* __restrict__ bhh1,
                    const float* __restrict__ Wlin, const float* __restrict__ blin,
                    float* __restrict__ out)
{
    const int b   = blockIdx.x;
    const int tid = threadIdx.x;
    const int m   = tid >> 2;   // h-index this group owns
    const int sl  = tid & 3;    // k-slice within the group

    __shared__ __align__(16) float trajs[TT * FIN];
    __shared__ __align__(16) float h0buf[2][HH];
    __shared__ __align__(16) float h1buf[2][HH];
    __shared__ __align__(16) float xin[WS][FIN];
    __shared__ float preds[NW * 2];
    __shared__ float red[128];
    __shared__ float wlin_s[128];
    __shared__ float blin_s[2];

    for (int i = tid; i < TT * FIN; i += 256) trajs[i] = traj[b * TT * FIN + i];
    if (tid < 128) wlin_s[tid] = Wlin[tid];
    if (tid < 2)   blin_s[tid] = blin[tid];

    // ---- weights -> registers. Thread (m,sl): 4 gate rows (i,f,g,o of index m),
    //      k-slice chunks {16c+4sl : c=0..3} of each 64-wide matrix. ----
    u64 whh0p[4][4][2], wih1p[4][4][2], whh1p[4][4][2];
    u64 wih0p0, wih0p1, b0p0, b0p1, b1p0, b1p1;
    {
        float wi[4], bb0[4], bb1[4];
        #pragma unroll
        for (int g = 0; g < 4; g++) {
            const int rg = 64 * g + m;
            wi[g]  = Wih0[rg * FIN + sl];
            bb0[g] = bih0[rg] + bhh0[rg];
            bb1[g] = bih1[rg] + bhh1[rg];
            #pragma unroll
            for (int c = 0; c < 4; c++) {
                const int k0 = 16 * c + 4 * sl;
                ulonglong2 v0 = *(const ulonglong2*)(Whh0 + rg * HH + k0);
                whh0p[g][c][0] = v0.x; whh0p[g][c][1] = v0.y;
                ulonglong2 v1 = *(const ulonglong2*)(Wih1 + rg * HH + k0);
                wih1p[g][c][0] = v1.x; wih1p[g][c][1] = v1.y;
                ulonglong2 v2 = *(const ulonglong2*)(Whh1 + rg * HH + k0);
                whh1p[g][c][0] = v2.x; whh1p[g][c][1] = v2.y;
            }
        }
        wih0p0 = pack2(wi[0], wi[1]);  wih0p1 = pack2(wi[2], wi[3]);
        b0p0 = pack2(bb0[0], bb0[1]);  b0p1 = pack2(bb0[2], bb0[3]);
        b1p0 = pack2(bb1[0], bb1[1]);  b1p1 = pack2(bb1[2], bb1[3]);
    }

    float c0 = 0.0f, c1 = 0.0f, h0v = 0.0f, h1v = 0.0f;
    __syncthreads();   // trajs staged

    for (int w = 0; w < NW; w++) {
        // ---- all 8 input rows for this window (depends only on prior preds) ----
        if (tid < 32) {
            const int s = tid >> 2, f = tid & 3;
            float v;
            if (w == 0) {
                v = trajs[s * FIN + f];
            } else if (w < WS) {
                if (s < WS - w) {
                    v = trajs[(w + s) * FIN + f];
                } else {
                    v = (f < 2) ? trajs[(2 * w + s - 1) * FIN + f]
                                : preds[(w + s - WS) * 2 + (f - 2)];
                }
            } else {
                v = (f < 2) ? trajs[(w + s) * FIN + f]
                            : preds[(w + s - WS) * 2 + (f - 2)];
            }
            xin[s][f] = v;
        }
        __syncthreads();

        // ---- s = 0 (zero initial state: h-terms dropped) ----
        {
            float xs = xin[0][sl];
            u64 xx = pack2(xs, xs);
            u64 X0 = 0, X1 = 0;
            fma2(X0, xx, wih0p0); fma2(X1, xx, wih0p1);
            u64 acc[4] = {0, 0, 0, 0};
            h0v = cell_epi(acc, X0, X1, b0p0, b0p1, c0, true);
            if (sl == 0) h0buf[0][m] = h0v;
            __syncthreads();
            u64 acc1[4] = {0, 0, 0, 0};
            dot64(acc1, h0buf[0], wih1p, sl);
            h1v = cell_epi(acc1, 0, 0, b1p0, b1p1, c1, true);
            if (sl == 0) h1buf[0][m] = h1v;
        }

        // ---- s = 1..7 : one barrier per step ----
        for (int s = 1; s < WS; s++) {
            const int pc = s & 1, pp = pc ^ 1;
            float xs = xin[s][sl];
            u64 xx = pack2(xs, xs);
            u64 X0 = 0, X1 = 0;
            fma2(X0, xx, wih0p0); fma2(X1, xx, wih0p1);
            u64 acc[4] = {0, 0, 0, 0};
            dot64(acc, h0buf[pp], whh0p, sl);
            h0v = cell_epi(acc, X0, X1, b0p0, b0p1, c0, false);
            if (sl == 0) h0buf[pc][m] = h0v;
            __syncthreads();
            u64 acc1[4] = {0, 0, 0, 0};
            dot64(acc1, h0buf[pc], wih1p, sl);
            dot64(acc1, h1buf[pp], whh1p, sl);
            h1v = cell_epi(acc1, 0, 0, b1p0, b1p1, c1, false);
            if (sl == 0) h1buf[pc][m] = h1v;
        }
        __syncthreads();   // h1(7) visible (parity 1)

        // ---- prediction: p[w] = p[w-1] + Wlin·h1 + blin ----
        if (tid < 128) {
            const int r = tid >> 6, k = tid & 63;
            red[tid] = wlin_s[r * 64 + k] * h1buf[1][k];
        }
        __syncthreads();
        if (tid < 2) {
            float d = blin_s[tid];
            #pragma unroll
            for (int k = 0; k < 64; k++) d += red[tid * 64 + k];
            const float prev = (w == 0) ? trajs[7 * FIN + 2 + tid]
                                        : preds[(w - 1) * 2 + tid];
            const float p = prev + d;
            preds[w * 2 + tid] = p;
            out[(b * NW + w) * 2 + tid] = p;
        }
        __syncthreads();
    }

    // ---- final states h[2,B,H], c[2,B,H] (group registers hold last h/c) ----
    if (sl == 0) {
        const int base = BB * NW * 2;
        out[base + 0 * BB * HH + b * HH + m] = h0v;
        out[base + 1 * BB * HH + b * HH + m] = h1v;
        out[base + 2 * BB * HH + b * HH + m] = c0;
        out[base + 3 * BB * HH + b * HH + m] = c1;
    }
}

extern "C" void kernel_launch(void* const* d_in, const int* in_sizes, int n_in,
                              void* d_out, int out_size) {
    const float* traj = (const float*)d_in[0];
    const float* Wih0 = (const float*)d_in[1];
    const float* Whh0 = (const float*)d_in[2];
    const float* bih0 = (const float*)d_in[3];
    const float* bhh0 = (const float*)d_in[4];
    const float* Wih1 = (const float*)d_in[5];
    const float* Whh1 = (const float*)d_in[6];
    const float* bih1 = (const float*)d_in[7];
    const float* bhh1 = (const float*)d_in[8];
    const float* Wlin = (const float*)d_in[9];
    const float* blin = (const float*)d_in[10];

    or_lstm_kernel<<<BB, 256>>>(traj, Wih0, Whh0, bih0, bhh0,
                                Wih1, Whh1, bih1, bhh1,
                                Wlin, blin, (float*)d_out);
}